// round 9
// baseline (speedup 1.0000x reference)
#include <cuda_runtime.h>
#include <math.h>

#define NMAX 200000
#define DFEAT 256
#define MNB   64
#define KSEL  3

// Scratch (allocation-free): per-node projections.
__device__ float g_s_self[NMAX];
__device__ float g_s_all[NMAX];

// ---------------------------------------------------------------------------
// Kernel 1: one node per 8-lane group (4 nodes/warp). Each lane loads 8
// float4 of its node's row up-front (MLP 8); W re-read via __ldg (2KB,
// L1-resident; lanes of a group cover one 128B line per step, shared by all
// 4 groups). Reduction: 3 shfl levels within the 8-lane group only.
// ---------------------------------------------------------------------------
__global__ void __launch_bounds__(256) score_kernel(const float* __restrict__ x,
                                                    const float* __restrict__ W,
                                                    const float* __restrict__ bias,
                                                    int N) {
    int warp = (blockIdx.x * 256 + threadIdx.x) >> 5;
    int lane = threadIdx.x & 31;
    int seg  = lane >> 3;                 // group id (0..3)
    int sub  = lane & 7;                  // lane within group
    int node = warp * 4 + seg;
    if (warp * 4 >= N) return;            // whole-warp guard
    int nn = node < N ? node : N - 1;     // clamp (edge warps)

    const float4* xr  = (const float4*)(x + (size_t)nn * DFEAT);
    const float4* wa4 = (const float4*)(W);          // W[0:256]
    const float4* wb4 = (const float4*)(W + DFEAT);  // W[256:512]

    float4 xv[8];
#pragma unroll
    for (int j = 0; j < 8; j++)
        xv[j] = __ldg(xr + sub + 8 * j);

    float ta = 0.f, tb = 0.f;
#pragma unroll
    for (int j = 0; j < 8; j++) {
        float4 c  = xv[j];
        float4 av = __ldg(wa4 + sub + 8 * j);
        float4 bv = __ldg(wb4 + sub + 8 * j);
        ta = fmaf(c.x, av.x, ta); ta = fmaf(c.y, av.y, ta);
        ta = fmaf(c.z, av.z, ta); ta = fmaf(c.w, av.w, ta);
        tb = fmaf(c.x, bv.x, tb); tb = fmaf(c.y, bv.y, tb);
        tb = fmaf(c.z, bv.z, tb); tb = fmaf(c.w, bv.w, tb);
    }

    // 3-level reduction within the 8-lane group (xor 4,2,1 stay in-group).
#pragma unroll
    for (int off = 4; off; off >>= 1) {
        ta += __shfl_xor_sync(0xffffffffu, ta, off);
        tb += __shfl_xor_sync(0xffffffffu, tb, off);
    }
    if (sub == 0 && node < N) {
        g_s_self[node] = ta + bias[0];
        g_s_all[node]  = tb;
    }
}

// Order-preserving float<->uint mapping (total order on floats).
__device__ __forceinline__ unsigned fkey(float f) {
    unsigned u = __float_as_uint(f);
    return (u & 0x80000000u) ? ~u : (u | 0x80000000u);
}
__device__ __forceinline__ float funkey(unsigned u) {
    unsigned b = (u & 0x80000000u) ? (u & 0x7fffffffu) : ~u;
    return __uint_as_float(b);
}

// ---------------------------------------------------------------------------
// Kernel 2: FOUR nodes per warp (8-lane segments), 8 candidate slots/lane.
// Only a 3-deep sorted head list is ever needed per lane (max 3 pops), so:
// two sort-4 networks (5 CSWAPs each) + 3-step branchless merge extracting
// the top-3 of the union. Rounds: segmented REDUX.max on h0 + ballot + ffs;
// winner stores the id directly and pops (2-pair shift). Values written by
// segment-lanes 0..2 with __expf. Gathers predicated on cnt.
// ---------------------------------------------------------------------------
__global__ void __launch_bounds__(256) topk_kernel(const int* __restrict__ neighbors,
                                                   const int* __restrict__ counts,
                                                   float* __restrict__ out,
                                                   int N) {
    int warp = (blockIdx.x * 256 + threadIdx.x) >> 5;
    int lane = threadIdx.x & 31;
    int seg  = lane >> 3;                 // segment id within warp (0..3)
    int sub  = lane & 7;                  // lane within segment
    int node = warp * 4 + seg;
    if (node >= N) return;

    unsigned mask = 0xFFu << (seg * 8);

    int cnt  = __ldg(counts + node);
    int base = sub * 8;

    const int4* nb = (const int4*)(neighbors + (size_t)node * MNB);
    int4 nA = __ldg(nb + sub * 2);         // positions base..base+3
    int4 nB = __ldg(nb + sub * 2 + 1);     // positions base+4..base+7

    // key 0 marks invalid; fkey(any float) > 0. Predicated-off gathers emit
    // no L1 wavefront. cnt >= K so the top-3 are always real entries.
    unsigned a0 = (base + 0 < cnt) ? fkey(__ldg(g_s_all + nA.x)) : 0u;
    unsigned a1 = (base + 1 < cnt) ? fkey(__ldg(g_s_all + nA.y)) : 0u;
    unsigned a2 = (base + 2 < cnt) ? fkey(__ldg(g_s_all + nA.z)) : 0u;
    unsigned a3 = (base + 3 < cnt) ? fkey(__ldg(g_s_all + nA.w)) : 0u;
    unsigned b0 = (base + 4 < cnt) ? fkey(__ldg(g_s_all + nB.x)) : 0u;
    unsigned b1 = (base + 5 < cnt) ? fkey(__ldg(g_s_all + nB.y)) : 0u;
    unsigned b2 = (base + 6 < cnt) ? fkey(__ldg(g_s_all + nB.z)) : 0u;
    unsigned b3 = (base + 7 < cnt) ? fkey(__ldg(g_s_all + nB.w)) : 0u;
    int ca0 = nA.x, ca1 = nA.y, ca2 = nA.z, ca3 = nA.w;
    int cb0 = nB.x, cb1 = nB.y, cb2 = nB.z, cb3 = nB.w;

    // Two sort-4 networks, descending.
#define CSWAP(ka, ga, kb, gb)                                        \
    { bool sw = (kb) > (ka);                                         \
      unsigned tk = sw ? (kb) : (ka); (kb) = sw ? (ka) : (kb); (ka) = tk; \
      int tg = sw ? (gb) : (ga); (gb) = sw ? (ga) : (gb); (ga) = tg; }
    CSWAP(a0, ca0, a1, ca1) CSWAP(a2, ca2, a3, ca3)
    CSWAP(a0, ca0, a2, ca2) CSWAP(a1, ca1, a3, ca3)
    CSWAP(a1, ca1, a2, ca2)
    CSWAP(b0, cb0, b1, cb1) CSWAP(b2, cb2, b3, cb3)
    CSWAP(b0, cb0, b2, cb2) CSWAP(b1, cb1, b3, cb3)
    CSWAP(b1, cb1, b2, cb2)
#undef CSWAP

    // Branchless merge: top-3 of the two sorted 4-lists. Shift depth shrinks
    // per step (4th-order statistics never needed).
    unsigned h0, h1, h2;
    int g0, g1, g2;
    {
        bool s = b0 > a0;                      // step 1
        h0 = s ? b0 : a0; g0 = s ? cb0 : ca0;
        unsigned na0 = s ? a0 : a1, na1 = s ? a1 : a2;
        int      nc0 = s ? ca0 : ca1, nc1 = s ? ca1 : ca2;
        unsigned nb0_ = s ? b1 : b0, nb1_ = s ? b2 : b1;
        int      nd0 = s ? cb1 : cb0, nd1 = s ? cb2 : cb1;

        s = nb0_ > na0;                        // step 2
        h1 = s ? nb0_ : na0; g1 = s ? nd0 : nc0;
        unsigned ma0 = s ? na0 : na1;
        int      mc0 = s ? nc0 : nc1;
        unsigned mb0 = s ? nb1_ : nb0_;
        int      md0 = s ? nd1 : nd0;

        s = mb0 > ma0;                         // step 3
        h2 = s ? mb0 : ma0; g2 = s ? md0 : mc0;
    }

    float* osel = out + (size_t)N * KSEL;
    size_t ob = (size_t)node * KSEL;

    unsigned w0, w1, w2;
#pragma unroll
    for (int t = 0; t < KSEL; t++) {
        unsigned m = __reduce_max_sync(mask, h0);
        unsigned bal = __ballot_sync(mask, h0 == m);    // non-mask bits are 0
        int wl = __ffs((int)bal) - 1;                   // absolute lane id

        if (t == 0) w0 = m; else if (t == 1) w1 = m; else w2 = m;

        if (lane == wl) {                               // winner: store id, pop
            osel[ob + t] = (float)g0;                   // exact: ids < 2^24
            h0 = h1; g0 = g1;
            h1 = h2; g1 = g2;
        }
    }

    if (sub < KSEL) {                                   // parallel value epilogue
        unsigned wk = (sub == 0) ? w0 : (sub == 1) ? w1 : w2;
        float v = g_s_self[node] + funkey(wk);
        v = fmaxf(v, 0.01f * v);                        // leaky_relu (jax default)
        out[ob + sub] = __expf(v);
    }
}

extern "C" void kernel_launch(void* const* d_in, const int* in_sizes, int n_in,
                              void* d_out, int out_size) {
    // metadata order: node_features, neighbors, neighbor_counts, W, b
    const float* x         = (const float*)d_in[0];
    const int*   neighbors = (const int*)d_in[1];
    const int*   counts    = (const int*)d_in[2];
    const float* W         = (const float*)d_in[3];
    const float* bias      = (const float*)d_in[4];

    int N = in_sizes[0] / DFEAT;
    if (N > NMAX) N = NMAX;

    int warps1  = (N + 3) / 4;               // 4 nodes per warp
    int blocks1 = (warps1 + 7) / 8;
    score_kernel<<<blocks1, 256>>>(x, W, bias, N);

    int warps2  = (N + 3) / 4;               // 4 nodes per warp
    int blocks2 = (warps2 + 7) / 8;
    topk_kernel<<<blocks2, 256>>>(neighbors, counts, (float*)d_out, N);
}

// round 11
// speedup vs baseline: 1.0314x; 1.0314x over previous
#include <cuda_runtime.h>
#include <math.h>

#define NMAX 200000
#define DFEAT 256
#define MNB   64
#define KSEL  3
#define NODES_PER_WARP 8

// Scratch (allocation-free): per-node projections.
__device__ float g_s_self[NMAX];
__device__ float g_s_all[NMAX];

// ---------------------------------------------------------------------------
// Kernel 1 (round-8 measured optimum, unchanged): one warp handles 8 nodes in
// 2 batches of 4. All 4 rows of a batch loaded up-front (8 LDG.128/lane in
// flight), W in registers, 4 independent interleaved butterfly reductions.
// ---------------------------------------------------------------------------
__global__ void __launch_bounds__(256) score_kernel(const float* __restrict__ x,
                                                    const float* __restrict__ W,
                                                    const float* __restrict__ bias,
                                                    int N) {
    int warp = (blockIdx.x * 256 + threadIdx.x) >> 5;
    int lane = threadIdx.x & 31;
    int node0 = warp * NODES_PER_WARP;
    if (node0 >= N) return;

    const float4* wa4 = (const float4*)(W);          // W[0:256]
    const float4* wb4 = (const float4*)(W + DFEAT);  // W[256:512]
    float4 a0 = __ldg(wa4 + lane), a1 = __ldg(wa4 + lane + 32);
    float4 b0 = __ldg(wb4 + lane), b1 = __ldg(wb4 + lane + 32);
    float bb = bias[0];

#pragma unroll
    for (int batch = 0; batch < NODES_PER_WARP; batch += 4) {
        int nb0 = node0 + batch;

        float4 v0[4], v1[4];
#pragma unroll
        for (int i = 0; i < 4; i++) {
            int n = nb0 + i;
            if (n < N) {
                const float4* xr = (const float4*)(x + (size_t)n * DFEAT);
                v0[i] = __ldg(xr + lane);
                v1[i] = __ldg(xr + lane + 32);
            }
        }

        float sa[4], sb[4];
#pragma unroll
        for (int i = 0; i < 4; i++) {
            float4 c0 = v0[i], c1 = v1[i];
            float ta, tb;
            ta  = c0.x * a0.x;          ta = fmaf(c0.y, a0.y, ta);
            ta  = fmaf(c0.z, a0.z, ta); ta = fmaf(c0.w, a0.w, ta);
            ta  = fmaf(c1.x, a1.x, ta); ta = fmaf(c1.y, a1.y, ta);
            ta  = fmaf(c1.z, a1.z, ta); ta = fmaf(c1.w, a1.w, ta);
            tb  = c0.x * b0.x;          tb = fmaf(c0.y, b0.y, tb);
            tb  = fmaf(c0.z, b0.z, tb); tb = fmaf(c0.w, b0.w, tb);
            tb  = fmaf(c1.x, b1.x, tb); tb = fmaf(c1.y, b1.y, tb);
            tb  = fmaf(c1.w, b1.w, tb); tb = fmaf(c1.z, b1.z, tb);
            sa[i] = ta; sb[i] = tb;
        }

        // 4 independent interleaved butterflies (8 shfls per level).
#pragma unroll
        for (int off = 16; off; off >>= 1) {
#pragma unroll
            for (int i = 0; i < 4; i++) {
                sa[i] += __shfl_xor_sync(0xffffffffu, sa[i], off);
                sb[i] += __shfl_xor_sync(0xffffffffu, sb[i], off);
            }
        }
        if (lane == 0) {
#pragma unroll
            for (int i = 0; i < 4; i++) {
                int n = nb0 + i;
                if (n < N) {
                    g_s_self[n] = sa[i] + bb;
                    g_s_all[n]  = sb[i];
                }
            }
        }
    }
}

// Order-preserving float<->uint mapping (total order on floats).
__device__ __forceinline__ unsigned fkey(float f) {
    unsigned u = __float_as_uint(f);
    return (u & 0x80000000u) ? ~u : (u | 0x80000000u);
}
__device__ __forceinline__ float funkey(unsigned u) {
    unsigned b = (u & 0x80000000u) ? (u & 0x7fffffffu) : ~u;
    return __uint_as_float(b);
}

// ---------------------------------------------------------------------------
// Kernel 2: FOUR nodes per warp (8-lane segments), 8 candidate slots/lane.
// Per-lane PRUNED partial sort: Batcher-8 with the 4 comparators that have no
// forward path to outputs {0,1,2} removed (15 CSWAPs, same stage structure /
// parallelism). Only head positions 0..2 are guaranteed sorted — exactly what
// the <=3 pops need. Rounds: segmented REDUX.max + ballot + ffs; winner
// stores the id directly and pops. Values by segment-lanes 0..2 with __expf.
// ---------------------------------------------------------------------------
__global__ void __launch_bounds__(256) topk_kernel(const int* __restrict__ neighbors,
                                                   const int* __restrict__ counts,
                                                   float* __restrict__ out,
                                                   int N) {
    int warp = (blockIdx.x * 256 + threadIdx.x) >> 5;
    int lane = threadIdx.x & 31;
    int seg  = lane >> 3;                 // segment id within warp (0..3)
    int sub  = lane & 7;                  // lane within segment
    int node = warp * 4 + seg;
    if (node >= N) return;

    unsigned mask = 0xFFu << (seg * 8);

    int cnt  = __ldg(counts + node);
    int base = sub * 8;

    // Prefetch epilogue operand early (hides one L2-latency gather).
    float ss = 0.f;
    if (sub < KSEL) ss = __ldg(g_s_self + node);

    const int4* nb = (const int4*)(neighbors + (size_t)node * MNB);
    int4 nA = __ldg(nb + sub * 2);         // positions base..base+3
    int4 nB = __ldg(nb + sub * 2 + 1);     // positions base+4..base+7

    unsigned k[8];
    int      c[8];
    c[0] = nA.x; c[1] = nA.y; c[2] = nA.z; c[3] = nA.w;
    c[4] = nB.x; c[5] = nB.y; c[6] = nB.z; c[7] = nB.w;
    // key 0 marks invalid; fkey(any float) > 0. Predicated-off gathers emit
    // no L1 wavefront. cnt >= K so the top-3 are always real entries.
#pragma unroll
    for (int i = 0; i < 8; i++)
        k[i] = (base + i < cnt) ? fkey(__ldg(g_s_all + c[i])) : 0u;

    // Pruned Batcher-8, descending: comparators with no path to outputs 0..2
    // removed (S4(3,7), S5(3,5), S6(3,4), S6(5,6)).
#define CSWAP(i, j)                                                     \
    { bool sw = k[j] > k[i];                                            \
      unsigned tk = sw ? k[j] : k[i]; k[j] = sw ? k[i] : k[j]; k[i] = tk; \
      int tc = sw ? c[j] : c[i]; c[j] = sw ? c[i] : c[j]; c[i] = tc; }
    CSWAP(0,1) CSWAP(2,3) CSWAP(4,5) CSWAP(6,7)   // S1
    CSWAP(0,2) CSWAP(1,3) CSWAP(4,6) CSWAP(5,7)   // S2
    CSWAP(1,2) CSWAP(5,6)                          // S3
    CSWAP(0,4) CSWAP(1,5) CSWAP(2,6)               // S4 (pruned (3,7))
    CSWAP(2,4)                                     // S5 (pruned (3,5))
    CSWAP(1,2)                                     // S6 (pruned (3,4),(5,6))
#undef CSWAP

    float* osel = out + (size_t)N * KSEL;
    size_t ob = (size_t)node * KSEL;

    unsigned w0, w1, w2;
#pragma unroll
    for (int t = 0; t < KSEL; t++) {
        unsigned m = __reduce_max_sync(mask, k[0]);
        unsigned bal = __ballot_sync(mask, k[0] == m);  // non-mask bits are 0
        int wl = __ffs((int)bal) - 1;                   // absolute lane id

        if (t == 0) w0 = m; else if (t == 1) w1 = m; else w2 = m;

        if (lane == wl) {                               // winner: store id, pop
            osel[ob + t] = (float)c[0];                 // exact: ids < 2^24
            k[0] = k[1]; c[0] = c[1];
            k[1] = k[2]; c[1] = c[2];
        }
    }

    if (sub < KSEL) {                                   // parallel value epilogue
        unsigned wk = (sub == 0) ? w0 : (sub == 1) ? w1 : w2;
        float v = ss + funkey(wk);
        v = fmaxf(v, 0.01f * v);                        // leaky_relu (jax default)
        out[ob + sub] = __expf(v);
    }
}

extern "C" void kernel_launch(void* const* d_in, const int* in_sizes, int n_in,
                              void* d_out, int out_size) {
    // metadata order: node_features, neighbors, neighbor_counts, W, b
    const float* x         = (const float*)d_in[0];
    const int*   neighbors = (const int*)d_in[1];
    const int*   counts    = (const int*)d_in[2];
    const float* W         = (const float*)d_in[3];
    const float* bias      = (const float*)d_in[4];

    int N = in_sizes[0] / DFEAT;
    if (N > NMAX) N = NMAX;

    int warps1  = (N + NODES_PER_WARP - 1) / NODES_PER_WARP;
    int blocks1 = (warps1 + 7) / 8;
    score_kernel<<<blocks1, 256>>>(x, W, bias, N);

    int warps2  = (N + 3) / 4;               // 4 nodes per warp
    int blocks2 = (warps2 + 7) / 8;
    topk_kernel<<<blocks2, 256>>>(neighbors, counts, (float*)d_out, N);
}

// round 12
// speedup vs baseline: 1.0349x; 1.0034x over previous
#include <cuda_runtime.h>
#include <math.h>

#define NMAX 200000
#define DFEAT 256
#define MNB   64
#define KSEL  3
#define NODES_PER_WARP 8

// Scratch (allocation-free): per-node projections.
__device__ float g_s_self[NMAX];
__device__ float g_s_all[NMAX];

// ---------------------------------------------------------------------------
// Kernel 1: one warp handles 8 nodes as four software-pipelined batches of 2.
// The next batch's 4 LDG.128/lane issue BEFORE the current batch's FMA+shfl
// window, so loads stay in flight continuously. Lookahead buffer is only 16
// floats/lane (~60 regs total — under the register cliff that killed the
// 4-node-lookahead variant). Reduction: 4 independent interleaved butterflies.
// ---------------------------------------------------------------------------
__global__ void __launch_bounds__(256) score_kernel(const float* __restrict__ x,
                                                    const float* __restrict__ W,
                                                    const float* __restrict__ bias,
                                                    int N) {
    int warp = (blockIdx.x * 256 + threadIdx.x) >> 5;
    int lane = threadIdx.x & 31;
    int node0 = warp * NODES_PER_WARP;
    if (node0 >= N) return;

    const float4* wa4 = (const float4*)(W);          // W[0:256]
    const float4* wb4 = (const float4*)(W + DFEAT);  // W[256:512]
    float4 a0 = __ldg(wa4 + lane), a1 = __ldg(wa4 + lane + 32);
    float4 b0 = __ldg(wb4 + lane), b1 = __ldg(wb4 + lane + 32);
    float bb = bias[0];

    // cur[2*i], cur[2*i+1] = two float4 halves of node i's row slice.
    float4 cur[4];
#pragma unroll
    for (int i = 0; i < 2; i++) {
        int n = node0 + i;
        if (n < N) {
            const float4* xr = (const float4*)(x + (size_t)n * DFEAT);
            cur[2 * i]     = __ldg(xr + lane);
            cur[2 * i + 1] = __ldg(xr + lane + 32);
        }
    }

#pragma unroll
    for (int batch = 0; batch < NODES_PER_WARP; batch += 2) {
        int nb0 = node0 + batch;

        float4 nxt[4];
        if (batch + 2 < NODES_PER_WARP) {            // prefetch next 2 nodes
#pragma unroll
            for (int i = 0; i < 2; i++) {
                int n = nb0 + 2 + i;
                if (n < N) {
                    const float4* xr = (const float4*)(x + (size_t)n * DFEAT);
                    nxt[2 * i]     = __ldg(xr + lane);
                    nxt[2 * i + 1] = __ldg(xr + lane + 32);
                }
            }
        }

        float sa[2], sb[2];
#pragma unroll
        for (int i = 0; i < 2; i++) {
            float4 c0 = cur[2 * i], c1 = cur[2 * i + 1];
            float ta, tb;
            ta  = c0.x * a0.x;          ta = fmaf(c0.y, a0.y, ta);
            ta  = fmaf(c0.z, a0.z, ta); ta = fmaf(c0.w, a0.w, ta);
            ta  = fmaf(c1.x, a1.x, ta); ta = fmaf(c1.y, a1.y, ta);
            ta  = fmaf(c1.z, a1.z, ta); ta = fmaf(c1.w, a1.w, ta);
            tb  = c0.x * b0.x;          tb = fmaf(c0.y, b0.y, tb);
            tb  = fmaf(c0.z, b0.z, tb); tb = fmaf(c0.w, b0.w, tb);
            tb  = fmaf(c1.x, b1.x, tb); tb = fmaf(c1.y, b1.y, tb);
            tb  = fmaf(c1.z, b1.z, tb); tb = fmaf(c1.w, b1.w, tb);
            sa[i] = ta; sb[i] = tb;
        }

        // 4 independent interleaved butterflies (4 shfls per level).
#pragma unroll
        for (int off = 16; off; off >>= 1) {
#pragma unroll
            for (int i = 0; i < 2; i++) {
                sa[i] += __shfl_xor_sync(0xffffffffu, sa[i], off);
                sb[i] += __shfl_xor_sync(0xffffffffu, sb[i], off);
            }
        }
        if (lane == 0) {
#pragma unroll
            for (int i = 0; i < 2; i++) {
                int n = nb0 + i;
                if (n < N) {
                    g_s_self[n] = sa[i] + bb;
                    g_s_all[n]  = sb[i];
                }
            }
        }

        if (batch + 2 < NODES_PER_WARP) {
#pragma unroll
            for (int j = 0; j < 4; j++) cur[j] = nxt[j];
        }
    }
}

// Order-preserving float<->uint mapping (total order on floats).
__device__ __forceinline__ unsigned fkey(float f) {
    unsigned u = __float_as_uint(f);
    return (u & 0x80000000u) ? ~u : (u | 0x80000000u);
}
__device__ __forceinline__ float funkey(unsigned u) {
    unsigned b = (u & 0x80000000u) ? (u & 0x7fffffffu) : ~u;
    return __uint_as_float(b);
}

// ---------------------------------------------------------------------------
// Kernel 2 (round-8 measured optimum, restored byte-for-byte): FOUR nodes per
// warp (8-lane segments), 8 candidate slots/lane. Per-lane Batcher-8 presort
// (19 compare-swaps) descending; 3 rounds touch only the per-lane HEAD:
// segmented REDUX.max + ballot + ffs; the winning lane stores the selected id
// DIRECTLY and pops its head. Values written by segment-lanes 0..2 with
// __expf. Gathers predicated on cnt (saves L1 wavefronts).
// ---------------------------------------------------------------------------
__global__ void __launch_bounds__(256) topk_kernel(const int* __restrict__ neighbors,
                                                   const int* __restrict__ counts,
                                                   float* __restrict__ out,
                                                   int N) {
    int warp = (blockIdx.x * 256 + threadIdx.x) >> 5;
    int lane = threadIdx.x & 31;
    int seg  = lane >> 3;                 // segment id within warp (0..3)
    int sub  = lane & 7;                  // lane within segment
    int node = warp * 4 + seg;
    if (node >= N) return;

    unsigned mask = 0xFFu << (seg * 8);

    int cnt  = __ldg(counts + node);
    int base = sub * 8;

    const int4* nb = (const int4*)(neighbors + (size_t)node * MNB);
    int4 nA = __ldg(nb + sub * 2);         // positions base..base+3
    int4 nB = __ldg(nb + sub * 2 + 1);     // positions base+4..base+7

    unsigned k[8];
    int      c[8];
    c[0] = nA.x; c[1] = nA.y; c[2] = nA.z; c[3] = nA.w;
    c[4] = nB.x; c[5] = nB.y; c[6] = nB.z; c[7] = nB.w;
    // key 0 marks invalid; fkey(any float) > 0. Predicated-off gathers emit
    // no L1 wavefront. cnt >= K so the top-3 are always real entries.
#pragma unroll
    for (int i = 0; i < 8; i++)
        k[i] = (base + i < cnt) ? fkey(__ldg(g_s_all + c[i])) : 0u;

    // Batcher odd-even mergesort for 8, descending (max kept at lower index).
#define CSWAP(i, j)                                                     \
    { bool sw = k[j] > k[i];                                            \
      unsigned tk = sw ? k[j] : k[i]; k[j] = sw ? k[i] : k[j]; k[i] = tk; \
      int tc = sw ? c[j] : c[i]; c[j] = sw ? c[i] : c[j]; c[i] = tc; }
    CSWAP(0,1) CSWAP(2,3) CSWAP(4,5) CSWAP(6,7)
    CSWAP(0,2) CSWAP(1,3) CSWAP(4,6) CSWAP(5,7)
    CSWAP(1,2) CSWAP(5,6)
    CSWAP(0,4) CSWAP(1,5) CSWAP(2,6) CSWAP(3,7)
    CSWAP(2,4) CSWAP(3,5)
    CSWAP(1,2) CSWAP(3,4) CSWAP(5,6)
#undef CSWAP

    float* osel = out + (size_t)N * KSEL;
    size_t ob = (size_t)node * KSEL;

    unsigned w0, w1, w2;
#pragma unroll
    for (int t = 0; t < KSEL; t++) {
        unsigned m = __reduce_max_sync(mask, k[0]);
        unsigned bal = __ballot_sync(mask, k[0] == m);  // non-mask bits are 0
        int wl = __ffs((int)bal) - 1;                   // absolute lane id

        if (t == 0) w0 = m; else if (t == 1) w1 = m; else w2 = m;

        if (lane == wl) {                               // winner: store id, pop
            osel[ob + t] = (float)c[0];                 // exact: ids < 2^24
#pragma unroll
            for (int i = 0; i < 7; i++) { k[i] = k[i + 1]; c[i] = c[i + 1]; }
        }
    }

    if (sub < KSEL) {                                   // parallel value epilogue
        unsigned wk = (sub == 0) ? w0 : (sub == 1) ? w1 : w2;
        float v = g_s_self[node] + funkey(wk);
        v = fmaxf(v, 0.01f * v);                        // leaky_relu (jax default)
        out[ob + sub] = __expf(v);
    }
}

extern "C" void kernel_launch(void* const* d_in, const int* in_sizes, int n_in,
                              void* d_out, int out_size) {
    // metadata order: node_features, neighbors, neighbor_counts, W, b
    const float* x         = (const float*)d_in[0];
    const int*   neighbors = (const int*)d_in[1];
    const int*   counts    = (const int*)d_in[2];
    const float* W         = (const float*)d_in[3];
    const float* bias      = (const float*)d_in[4];

    int N = in_sizes[0] / DFEAT;
    if (N > NMAX) N = NMAX;

    int warps1  = (N + NODES_PER_WARP - 1) / NODES_PER_WARP;
    int blocks1 = (warps1 + 7) / 8;
    score_kernel<<<blocks1, 256>>>(x, W, bias, N);

    int warps2  = (N + 3) / 4;               // 4 nodes per warp
    int blocks2 = (warps2 + 7) / 8;
    topk_kernel<<<blocks2, 256>>>(neighbors, counts, (float*)d_out, N);
}

// round 13
// speedup vs baseline: 1.1033x; 1.0661x over previous
#include <cuda_runtime.h>
#include <math.h>

#define NMAX 200000
#define DFEAT 256
#define MNB   64
#define KSEL  3
#define NODES_PER_WARP 8

// Scratch (allocation-free): per-node projections.
__device__ float g_s_self[NMAX];
__device__ float g_s_all[NMAX];

__device__ __forceinline__ float4 ldcs4(const float4* p) {
    return __ldcs(p);          // evict-first streaming load
}

// ---------------------------------------------------------------------------
// Kernel 1: one warp handles 8 nodes as four software-pipelined batches of 2.
// x rows loaded with __ldcs (read-once stream; evict-first protects the
// g_s_all lines this kernel writes, improving topk's L2 hit rate).
// ---------------------------------------------------------------------------
__global__ void __launch_bounds__(256) score_kernel(const float* __restrict__ x,
                                                    const float* __restrict__ W,
                                                    const float* __restrict__ bias,
                                                    int N) {
    int warp = (blockIdx.x * 256 + threadIdx.x) >> 5;
    int lane = threadIdx.x & 31;
    int node0 = warp * NODES_PER_WARP;
    if (node0 >= N) return;

    const float4* wa4 = (const float4*)(W);          // W[0:256]
    const float4* wb4 = (const float4*)(W + DFEAT);  // W[256:512]
    float4 a0 = __ldg(wa4 + lane), a1 = __ldg(wa4 + lane + 32);
    float4 b0 = __ldg(wb4 + lane), b1 = __ldg(wb4 + lane + 32);
    float bb = bias[0];

    float4 cur[4];
#pragma unroll
    for (int i = 0; i < 2; i++) {
        int n = node0 + i;
        if (n < N) {
            const float4* xr = (const float4*)(x + (size_t)n * DFEAT);
            cur[2 * i]     = ldcs4(xr + lane);
            cur[2 * i + 1] = ldcs4(xr + lane + 32);
        }
    }

#pragma unroll
    for (int batch = 0; batch < NODES_PER_WARP; batch += 2) {
        int nb0 = node0 + batch;

        float4 nxt[4];
        if (batch + 2 < NODES_PER_WARP) {            // prefetch next 2 nodes
#pragma unroll
            for (int i = 0; i < 2; i++) {
                int n = nb0 + 2 + i;
                if (n < N) {
                    const float4* xr = (const float4*)(x + (size_t)n * DFEAT);
                    nxt[2 * i]     = ldcs4(xr + lane);
                    nxt[2 * i + 1] = ldcs4(xr + lane + 32);
                }
            }
        }

        float sa[2], sb[2];
#pragma unroll
        for (int i = 0; i < 2; i++) {
            float4 c0 = cur[2 * i], c1 = cur[2 * i + 1];
            float ta, tb;
            ta  = c0.x * a0.x;          ta = fmaf(c0.y, a0.y, ta);
            ta  = fmaf(c0.z, a0.z, ta); ta = fmaf(c0.w, a0.w, ta);
            ta  = fmaf(c1.x, a1.x, ta); ta = fmaf(c1.y, a1.y, ta);
            ta  = fmaf(c1.z, a1.z, ta); ta = fmaf(c1.w, a1.w, ta);
            tb  = c0.x * b0.x;          tb = fmaf(c0.y, b0.y, tb);
            tb  = fmaf(c0.z, b0.z, tb); tb = fmaf(c0.w, b0.w, tb);
            tb  = fmaf(c1.x, b1.x, tb); tb = fmaf(c1.y, b1.y, tb);
            tb  = fmaf(c1.z, b1.z, tb); tb = fmaf(c1.w, b1.w, tb);
            sa[i] = ta; sb[i] = tb;
        }

#pragma unroll
        for (int off = 16; off; off >>= 1) {
#pragma unroll
            for (int i = 0; i < 2; i++) {
                sa[i] += __shfl_xor_sync(0xffffffffu, sa[i], off);
                sb[i] += __shfl_xor_sync(0xffffffffu, sb[i], off);
            }
        }
        if (lane == 0) {
#pragma unroll
            for (int i = 0; i < 2; i++) {
                int n = nb0 + i;
                if (n < N) {
                    g_s_self[n] = sa[i] + bb;
                    g_s_all[n]  = sb[i];
                }
            }
        }

        if (batch + 2 < NODES_PER_WARP) {
#pragma unroll
            for (int j = 0; j < 4; j++) cur[j] = nxt[j];
        }
    }
}

// Order-preserving float<->uint mapping (total order on floats).
__device__ __forceinline__ unsigned fkey(float f) {
    unsigned u = __float_as_uint(f);
    return (u & 0x80000000u) ? ~u : (u | 0x80000000u);
}
__device__ __forceinline__ float funkey(unsigned u) {
    unsigned b = (u & 0x80000000u) ? (u & 0x7fffffffu) : ~u;
    return __uint_as_float(b);
}

// ---------------------------------------------------------------------------
// Kernel 2: round-8 structure (4 nodes/warp, 8-lane segments, Batcher-8,
// head-pop rounds) with two trims:
//  (1) FLOAT-DOMAIN ranking: sort raw floats (invalid = -inf); fkey applied
//      only to the per-round head for REDUX; value recovered via funkey once
//      per round. Removes 8 gather-side fkeys + epilogue funkey.
//  (2) second neighbor int4 predicated on nvalid>4 (avg cnt~33 halves nB
//      traffic; predicated load, no divergent region).
// ---------------------------------------------------------------------------
__global__ void __launch_bounds__(256) topk_kernel(const int* __restrict__ neighbors,
                                                   const int* __restrict__ counts,
                                                   float* __restrict__ out,
                                                   int N) {
    int warp = (blockIdx.x * 256 + threadIdx.x) >> 5;
    int lane = threadIdx.x & 31;
    int seg  = lane >> 3;                 // segment id within warp (0..3)
    int sub  = lane & 7;                  // lane within segment
    int node = warp * 4 + seg;
    if (node >= N) return;

    unsigned mask = 0xFFu << (seg * 8);
    const float NEGINF = __int_as_float(0xff800000);

    int cnt    = __ldg(counts + node);
    int base   = sub * 8;
    int nvalid = cnt - base;              // slots [0, nvalid) are live

    const int4* nb = (const int4*)(neighbors + (size_t)node * MNB);
    int4 nA = __ldg(nb + sub * 2);                          // slots 0..3
    int4 nB = (nvalid > 4) ? __ldg(nb + sub * 2 + 1)        // slots 4..7
                           : make_int4(0, 0, 0, 0);

    float k[8];
    int   c[8];
    c[0] = nA.x; c[1] = nA.y; c[2] = nA.z; c[3] = nA.w;
    c[4] = nB.x; c[5] = nB.y; c[6] = nB.z; c[7] = nB.w;
    // -inf marks invalid. Predicated-off gathers emit no L1 wavefront.
    // cnt >= K so the top-3 are always real entries.
#pragma unroll
    for (int i = 0; i < 8; i++)
        k[i] = (i < nvalid) ? __ldg(g_s_all + c[i]) : NEGINF;

    // Batcher odd-even mergesort for 8, descending (float compares).
#define CSWAP(i, j)                                                     \
    { bool sw = k[j] > k[i];                                            \
      float tk = sw ? k[j] : k[i]; k[j] = sw ? k[i] : k[j]; k[i] = tk;  \
      int tc = sw ? c[j] : c[i]; c[j] = sw ? c[i] : c[j]; c[i] = tc; }
    CSWAP(0,1) CSWAP(2,3) CSWAP(4,5) CSWAP(6,7)
    CSWAP(0,2) CSWAP(1,3) CSWAP(4,6) CSWAP(5,7)
    CSWAP(1,2) CSWAP(5,6)
    CSWAP(0,4) CSWAP(1,5) CSWAP(2,6) CSWAP(3,7)
    CSWAP(2,4) CSWAP(3,5)
    CSWAP(1,2) CSWAP(3,4) CSWAP(5,6)
#undef CSWAP

    float* osel = out + (size_t)N * KSEL;
    size_t ob = (size_t)node * KSEL;

    float w0, w1, w2;
#pragma unroll
    for (int t = 0; t < KSEL; t++) {
        unsigned m = __reduce_max_sync(mask, fkey(k[0]));
        float mf = funkey(m);                            // exact round trip
        unsigned bal = __ballot_sync(mask, k[0] == mf);  // non-mask bits are 0
        int wl = __ffs((int)bal) - 1;                    // absolute lane id

        if (t == 0) w0 = mf; else if (t == 1) w1 = mf; else w2 = mf;

        if (lane == wl) {                                // winner: store id, pop
            osel[ob + t] = (float)c[0];                  // exact: ids < 2^24
#pragma unroll
            for (int i = 0; i < 7; i++) { k[i] = k[i + 1]; c[i] = c[i + 1]; }
        }
    }

    if (sub < KSEL) {                                    // parallel value epilogue
        float wv = (sub == 0) ? w0 : (sub == 1) ? w1 : w2;
        float v = g_s_self[node] + wv;
        v = fmaxf(v, 0.01f * v);                         // leaky_relu (jax default)
        out[ob + sub] = __expf(v);
    }
}

extern "C" void kernel_launch(void* const* d_in, const int* in_sizes, int n_in,
                              void* d_out, int out_size) {
    // metadata order: node_features, neighbors, neighbor_counts, W, b
    const float* x         = (const float*)d_in[0];
    const int*   neighbors = (const int*)d_in[1];
    const int*   counts    = (const int*)d_in[2];
    const float* W         = (const float*)d_in[3];
    const float* bias      = (const float*)d_in[4];

    int N = in_sizes[0] / DFEAT;
    if (N > NMAX) N = NMAX;

    int warps1  = (N + NODES_PER_WARP - 1) / NODES_PER_WARP;
    int blocks1 = (warps1 + 7) / 8;
    score_kernel<<<blocks1, 256>>>(x, W, bias, N);

    int warps2  = (N + 3) / 4;               // 4 nodes per warp
    int blocks2 = (warps2 + 7) / 8;
    topk_kernel<<<blocks2, 256>>>(neighbors, counts, (float*)d_out, N);
}